// round 4
// baseline (speedup 1.0000x reference)
#include <cuda_runtime.h>
#include <math.h>

// Problem constants (fixed by the dataset)
#define NN   50000
#define EE   800000
#define HH   8
#define CCH  32
#define HC   256
#define NB_SCAN 49   // ceil(NN/1024)

// ---------------- device scratch (allocation-free: static globals) ----------
__device__ float g_q[(size_t)NN * HC];              // 51.2 MB
__device__ float g_k[(size_t)NN * HC];              // 51.2 MB
__device__ float g_v[(size_t)NN * HC];              // 51.2 MB
__device__ float g_P[(size_t)NN * HH * 256];        // 409.6 MB  P[n,h,i]
__device__ float g_A[(size_t)NN * HH * 256];        // 409.6 MB  A[n,h,i] (alpha-weighted ea)
__device__ int   g_deg[NN];
__device__ int   g_off[NN + 1];
__device__ int   g_cur[NN];
__device__ int   g_incl[NN];
__device__ int   g_bsum[64];
__device__ int   g_bpre[64];
__device__ int   g_srcs[EE];
__device__ int   g_perm[EE];                        // sorted position -> original edge id
__device__ int   g_is64;

// ---------------- dtype sniffer ---------------------------------------------
__global__ void k_detect(const long long* __restrict__ ei) {
    if (threadIdx.x == 0 && blockIdx.x == 0) {
        int ok = 1;
        for (int i = 0; i < 64; i++) {
            long long v = ei[i];
            if (v < 0 || v >= NN) ok = 0;
        }
        g_is64 = ok;
    }
}

__device__ __forceinline__ int load_idx(const void* ei, size_t pos, int is64) {
    if (is64) return (int)((const long long*)ei)[pos];
    return ((const int*)ei)[pos];
}

// ---------------- counting sort by destination ------------------------------
__global__ void k_zero_deg() {
    int i = blockIdx.x * blockDim.x + threadIdx.x;
    if (i < NN) g_deg[i] = 0;
}

__global__ void k_hist(const void* __restrict__ ei) {
    int e = blockIdx.x * blockDim.x + threadIdx.x;
    if (e < EE) {
        int d = load_idx(ei, (size_t)EE + e, g_is64);
        if ((unsigned)d < NN) atomicAdd(&g_deg[d], 1);
    }
}

__global__ void k_scan1() {
    __shared__ int sh[1024];
    int t = threadIdx.x;
    int i = blockIdx.x * 1024 + t;
    int v = (i < NN) ? g_deg[i] : 0;
    sh[t] = v;
    __syncthreads();
    #pragma unroll
    for (int off = 1; off < 1024; off <<= 1) {
        int add = (t >= off) ? sh[t - off] : 0;
        __syncthreads();
        sh[t] += add;
        __syncthreads();
    }
    if (i < NN) g_incl[i] = sh[t];
    if (t == 1023) g_bsum[blockIdx.x] = sh[t];
}

__global__ void k_scan2() {
    if (threadIdx.x == 0) {
        int run = 0;
        for (int b = 0; b < NB_SCAN; b++) {
            g_bpre[b] = run;
            run += g_bsum[b];
        }
    }
}

__global__ void k_scan3() {
    int i = blockIdx.x * blockDim.x + threadIdx.x;
    if (i < NN) {
        int incl = g_incl[i] + g_bpre[i >> 10];
        g_off[i + 1] = incl;
        g_cur[i]     = incl - g_deg[i];
    }
    if (i == 0) g_off[0] = 0;
}

__global__ void k_scatter(const void* __restrict__ ei) {
    int e = blockIdx.x * blockDim.x + threadIdx.x;
    if (e < EE) {
        int is64 = g_is64;
        int d = load_idx(ei, (size_t)EE + e, is64);
        int s = load_idx(ei, (size_t)e, is64);
        if ((unsigned)d < NN && (unsigned)s < NN) {
            int pos = atomicAdd(&g_cur[d], 1);
            if ((unsigned)pos < EE) {
                g_perm[pos] = e;
                g_srcs[pos] = s;
            }
        }
    }
}

// ---------------- fp32 SGEMM 128x128x16, fused q/k/v/skip (blockIdx.z) ------
__global__ __launch_bounds__(256, 2)
void k_sgemm4(const float* __restrict__ x,
              const float* __restrict__ Wq, const float* __restrict__ bq,
              const float* __restrict__ Wk, const float* __restrict__ bk,
              const float* __restrict__ Wv, const float* __restrict__ bv,
              const float* __restrict__ Ws, const float* __restrict__ bs,
              float* __restrict__ dout) {
    const float* B; const float* bias; float* Cout;
    switch (blockIdx.z) {
        case 0: B = Wq; bias = bq; Cout = g_q; break;
        case 1: B = Wk; bias = bk; Cout = g_k; break;
        case 2: B = Wv; bias = bv; Cout = g_v; break;
        default: B = Ws; bias = bs; Cout = dout; break;
    }
    const int M = NN;

    __shared__ float As[16][128];
    __shared__ float Bs[16][128];

    int t  = threadIdx.x;
    int bm = blockIdx.x * 128;
    int bn = blockIdx.y * 128;
    int tx = t & 15, ty = t >> 4;

    float acc[8][8];
    #pragma unroll
    for (int i = 0; i < 8; i++)
        #pragma unroll
        for (int j = 0; j < 8; j++) acc[i][j] = 0.f;

    int ar = t >> 2,  ac = (t & 3) * 4;
    int bk_ = t >> 5, bc = (t & 31) * 4;

    for (int k0 = 0; k0 < 256; k0 += 16) {
        #pragma unroll
        for (int i = 0; i < 2; i++) {
            int row = bm + ar + i * 64;
            int rr  = (row < M) ? row : (M - 1);
            float4 a = *(const float4*)(x + (size_t)rr * 256 + k0 + ac);
            As[ac + 0][ar + i * 64] = a.x;
            As[ac + 1][ar + i * 64] = a.y;
            As[ac + 2][ar + i * 64] = a.z;
            As[ac + 3][ar + i * 64] = a.w;
        }
        #pragma unroll
        for (int i = 0; i < 2; i++) {
            float4 b = *(const float4*)(B + (size_t)(k0 + bk_ + i * 8) * 256 + bn + bc);
            *(float4*)&Bs[bk_ + i * 8][bc] = b;
        }
        __syncthreads();
        #pragma unroll
        for (int kk = 0; kk < 16; kk++) {
            float ra[8], rb[8];
            *(float4*)(ra)     = *(float4*)&As[kk][ty * 8];
            *(float4*)(ra + 4) = *(float4*)&As[kk][ty * 8 + 4];
            *(float4*)(rb)     = *(float4*)&Bs[kk][tx * 8];
            *(float4*)(rb + 4) = *(float4*)&Bs[kk][tx * 8 + 4];
            #pragma unroll
            for (int i = 0; i < 8; i++)
                #pragma unroll
                for (int j = 0; j < 8; j++)
                    acc[i][j] = fmaf(ra[i], rb[j], acc[i][j]);
        }
        __syncthreads();
    }

    float bb[8];
    #pragma unroll
    for (int j = 0; j < 8; j++) bb[j] = bias[bn + tx * 8 + j];

    #pragma unroll
    for (int i = 0; i < 8; i++) {
        int row = bm + ty * 8 + i;
        if (row < M) {
            float* cptr = Cout + (size_t)row * 256 + bn + tx * 8;
            float4 o0, o1;
            o0.x = acc[i][0] + bb[0]; o0.y = acc[i][1] + bb[1];
            o0.z = acc[i][2] + bb[2]; o0.w = acc[i][3] + bb[3];
            o1.x = acc[i][4] + bb[4]; o1.y = acc[i][5] + bb[5];
            o1.z = acc[i][6] + bb[6]; o1.w = acc[i][7] + bb[7];
            *(float4*)(cptr)     = o0;
            *(float4*)(cptr + 4) = o1;
        }
    }
}

// ---------------- P GEMM: P[n,h,i] = sum_c q[n,h*32+c] * We[i,h*32+c] -------
__global__ __launch_bounds__(256)
void k_pgemm(const float* __restrict__ We) {
    __shared__ float qs[64][33];
    __shared__ float Wt[32][257];
    int h  = blockIdx.y;
    int n0 = blockIdx.x * 64;
    int t  = threadIdx.x;

    for (int idx = t; idx < 64 * 32; idx += 256) {
        int node = idx >> 5, c = idx & 31;
        int n = n0 + node;
        qs[node][c] = (n < NN) ? g_q[(size_t)n * 256 + h * 32 + c] : 0.f;
    }
    for (int idx = t; idx < 256 * 32; idx += 256) {
        int i = idx >> 5, c = idx & 31;
        Wt[c][i] = We[(size_t)i * 256 + h * 32 + c];
    }
    __syncthreads();

    int tx = t & 31;
    int ty = t >> 5;
    float acc[8][8];
    #pragma unroll
    for (int r = 0; r < 8; r++)
        #pragma unroll
        for (int ii = 0; ii < 8; ii++) acc[r][ii] = 0.f;

    #pragma unroll 4
    for (int c = 0; c < 32; c++) {
        float a[8], b[8];
        #pragma unroll
        for (int r = 0; r < 8; r++) a[r] = qs[ty * 8 + r][c];
        #pragma unroll
        for (int ii = 0; ii < 8; ii++) b[ii] = Wt[c][tx + ii * 32];
        #pragma unroll
        for (int r = 0; r < 8; r++)
            #pragma unroll
            for (int ii = 0; ii < 8; ii++)
                acc[r][ii] = fmaf(a[r], b[ii], acc[r][ii]);
    }

    #pragma unroll
    for (int r = 0; r < 8; r++) {
        int n = n0 + ty * 8 + r;
        if (n < NN) {
            float* Pr = g_P + ((size_t)n * 8 + h) * 256;
            #pragma unroll
            for (int ii = 0; ii < 8; ii++)
                Pr[tx + ii * 32] = acc[r][ii];
        }
    }
}

// ---------------- edge pass: 4-edge batches, online softmax -----------------
__global__ __launch_bounds__(256)
void k_edge(const float* __restrict__ ea, float* __restrict__ out) {
    __shared__ float eas[4][256];
    __shared__ int   s_src[4];
    int n    = blockIdx.x;
    int t    = threadIdx.x;
    int h    = t >> 5;
    int lane = t & 31;

    int begin = g_off[n], end = g_off[n + 1];
    size_t nb = (size_t)n * 256 + h * 32 + lane;
    const float scale = 0.17677669529663687f;     // 1/sqrt(32)
    float qv = g_q[nb] * scale;

    const float* Pr = g_P + ((size_t)n * 8 + h) * 256;
    float preg[8];
    #pragma unroll
    for (int j = 0; j < 8; j++) preg[j] = __ldcs(Pr + j * 32 + lane) * scale;

    float m = -INFINITY, l = 0.f, vacc = 0.f;
    float A[8];
    #pragma unroll
    for (int j = 0; j < 8; j++) A[j] = 0.f;

    int r_ld  = t >> 6;          // which of the 4 rows this thread loads
    int c_ld  = (t & 63) * 4;    // float4 column within the row

    for (int idx0 = begin; idx0 < end; idx0 += 4) {
        int nbatch = end - idx0; if (nbatch > 4) nbatch = 4;

        // ---- load phase: 4 ea rows (4KB) + 4 src ids, all in flight ----
        {
            int ide = idx0 + r_ld;
            int eo  = g_perm[(ide < end) ? ide : (end - 1)];
            float4 v4 = *(const float4*)(ea + (size_t)eo * 256 + c_ld);
            if (t < 4) {
                int ids = idx0 + t;
                s_src[t] = g_srcs[(ids < end) ? ids : (end - 1)];
            }
            *(float4*)&eas[r_ld][c_ld] = v4;
        }
        __syncthreads();

        // ---- prefetch k/v lane elements for all 4 srcs (MLP=8) ----
        float kv4[4], vv4[4];
        int src4[4];
        #pragma unroll
        for (int r = 0; r < 4; r++) src4[r] = s_src[r];
        #pragma unroll
        for (int r = 0; r < 4; r++) {
            size_t sb = (size_t)src4[r] * 256 + h * 32 + lane;
            kv4[r] = g_k[sb];
            vv4[r] = g_v[sb];
        }

        // ---- 4 score partials, reductions interleaved (ILP=4) ----
        float sr[4];
        #pragma unroll
        for (int r = 0; r < 4; r++) {
            float s = qv * kv4[r];
            #pragma unroll
            for (int j = 0; j < 8; j++)
                s = fmaf(preg[j], eas[r][j * 32 + lane], s);
            sr[r] = s;
        }
        #pragma unroll
        for (int o = 16; o; o >>= 1) {
            #pragma unroll
            for (int r = 0; r < 4; r++)
                sr[r] += __shfl_xor_sync(0xffffffffu, sr[r], o);
        }

        // ---- sequential softmax updates (cheap) ----
        #pragma unroll
        for (int r = 0; r < 4; r++) {
            if (r < nbatch) {
                float s  = sr[r];
                float nm = fmaxf(m, s);
                float cf = __expf(m - nm);
                float p  = __expf(s - nm);
                l    = l * cf + p;
                vacc = vacc * cf + p * vv4[r];
                #pragma unroll
                for (int j = 0; j < 8; j++)
                    A[j] = A[j] * cf + p * eas[r][j * 32 + lane];
                m = nm;
            }
        }
        __syncthreads();
    }

    float inv = (l > 0.f) ? (1.f / l) : 0.f;
    out[nb] += vacc * inv;
    float* Ar = g_A + ((size_t)n * 8 + h) * 256;
    #pragma unroll
    for (int j = 0; j < 8; j++) Ar[j * 32 + lane] = A[j] * inv;
}

// ---------------- A GEMM: out[n,h*32+c] += sum_i A[n,h,i] * We[i,h*32+c] ----
__global__ __launch_bounds__(256)
void k_agemm(const float* __restrict__ We, float* __restrict__ out) {
    __shared__ float As[64][65];
    __shared__ float Ws[64][33];
    int h  = blockIdx.y;
    int n0 = blockIdx.x * 64;
    int t  = threadIdx.x;
    int tx = t & 31;
    int ty = t >> 5;

    float acc[8];
    #pragma unroll
    for (int r = 0; r < 8; r++) acc[r] = 0.f;

    for (int k0 = 0; k0 < 256; k0 += 64) {
        __syncthreads();
        for (int idx = t; idx < 64 * 64; idx += 256) {
            int node = idx >> 6, kk = idx & 63;
            int n = n0 + node;
            As[node][kk] = (n < NN)
                ? __ldcs(g_A + ((size_t)n * 8 + h) * 256 + k0 + kk) : 0.f;
        }
        for (int idx = t; idx < 64 * 32; idx += 256) {
            int kk = idx >> 5, c = idx & 31;
            Ws[kk][c] = We[(size_t)(k0 + kk) * 256 + h * 32 + c];
        }
        __syncthreads();
        #pragma unroll 8
        for (int kk = 0; kk < 64; kk++) {
            float b = Ws[kk][tx];
            #pragma unroll
            for (int r = 0; r < 8; r++)
                acc[r] = fmaf(As[ty * 8 + r][kk], b, acc[r]);
        }
    }

    #pragma unroll
    for (int r = 0; r < 8; r++) {
        int n = n0 + ty * 8 + r;
        if (n < NN)
            out[(size_t)n * 256 + h * 32 + tx] += acc[r];
    }
}

// ---------------- launch ----------------------------------------------------
extern "C" void kernel_launch(void* const* d_in, const int* in_sizes, int n_in,
                              void* d_out, int out_size) {
    const float* x  = (const float*)d_in[0];
    const void*  ei = d_in[1];
    const float* ea = (const float*)d_in[2];
    const float* Wq = (const float*)d_in[3];
    const float* bq = (const float*)d_in[4];
    const float* Wk = (const float*)d_in[5];
    const float* bk = (const float*)d_in[6];
    const float* Wv = (const float*)d_in[7];
    const float* bv = (const float*)d_in[8];
    const float* We = (const float*)d_in[9];
    const float* Ws = (const float*)d_in[10];
    const float* bs = (const float*)d_in[11];
    float* out = (float*)d_out;

    // 0) sniff edge_index dtype
    k_detect<<<1, 32>>>((const long long*)ei);

    // 1) CSR sort by destination
    k_zero_deg<<<(NN + 255) / 256, 256>>>();
    k_hist<<<(EE + 255) / 256, 256>>>(ei);
    k_scan1<<<NB_SCAN, 1024>>>();
    k_scan2<<<1, 32>>>();
    k_scan3<<<(NN + 255) / 256, 256>>>();
    k_scatter<<<(EE + 255) / 256, 256>>>(ei);

    // 2) node GEMMs: q, k, v, skip — one fused launch (z picks weights)
    dim3 gn((NN + 127) / 128, 2, 4);
    k_sgemm4<<<gn, 256>>>(x, Wq, bq, Wk, bk, Wv, bv, Ws, bs, out);

    // 3) P[n,h,i] = We_h @ q_h  (score projection)
    dim3 gp((NN + 63) / 64, 8);
    k_pgemm<<<gp, 256>>>(We);

    // 4) edge pass: scores via ea.P, online softmax, accumulate vacc and A
    k_edge<<<NN, 256>>>(ea, out);

    // 5) out += A @ We (per head slice)
    k_agemm<<<gp, 256>>>(We, out);
}

// round 7
// speedup vs baseline: 1.2745x; 1.2745x over previous
#include <cuda_runtime.h>
#include <cstdint>
#include <math.h>

// Problem constants (fixed by the dataset)
#define NN   50000
#define EE   800000
#define HH   8
#define CCH  32
#define HC   256
#define NB_SCAN 49   // ceil(NN/1024)
#define EST  4       // edge pipeline stages

// ---------------- device scratch (allocation-free: static globals) ----------
__device__ float g_q[(size_t)NN * HC];
__device__ float g_k[(size_t)NN * HC];
__device__ float g_v[(size_t)NN * HC];
__device__ float g_P[(size_t)NN * HH * 256];        // P[n,h,i]
__device__ float g_A[(size_t)NN * HH * 256];        // alpha-weighted ea accumulators
__device__ int   g_deg[NN];
__device__ int   g_off[NN + 1];
__device__ int   g_cur[NN];
__device__ int   g_incl[NN];
__device__ int   g_bsum[64];
__device__ int   g_srcs[EE];
__device__ int   g_perm[EE];
__device__ int   g_is64;

// ---------------- init: dtype sniff + zero degree ---------------------------
__global__ void k_init(const long long* __restrict__ ei) {
    int i = blockIdx.x * blockDim.x + threadIdx.x;
    if (i < NN) g_deg[i] = 0;
    if (i == 0) {
        int ok = 1;
        for (int j = 0; j < 64; j++) {
            long long v = ei[j];
            if (v < 0 || v >= NN) ok = 0;
        }
        g_is64 = ok;
    }
}

__device__ __forceinline__ int load_idx(const void* ei, size_t pos, int is64) {
    if (is64) return (int)((const long long*)ei)[pos];
    return ((const int*)ei)[pos];
}

__global__ void k_hist(const void* __restrict__ ei) {
    int e = blockIdx.x * blockDim.x + threadIdx.x;
    if (e < EE) {
        int d = load_idx(ei, (size_t)EE + e, g_is64);
        if ((unsigned)d < NN) atomicAdd(&g_deg[d], 1);
    }
}

__global__ void k_scan1() {
    __shared__ int sh[1024];
    int t = threadIdx.x;
    int i = blockIdx.x * 1024 + t;
    int v = (i < NN) ? g_deg[i] : 0;
    sh[t] = v;
    __syncthreads();
    #pragma unroll
    for (int off = 1; off < 1024; off <<= 1) {
        int add = (t >= off) ? sh[t - off] : 0;
        __syncthreads();
        sh[t] += add;
        __syncthreads();
    }
    if (i < NN) g_incl[i] = sh[t];
    if (t == 1023) g_bsum[blockIdx.x] = sh[t];
}

// fused scan2+scan3: each block rebuilds the 49-entry block-sum prefix locally
__global__ void k_scan23() {
    __shared__ int bpre[NB_SCAN + 1];
    int t = threadIdx.x;
    if (t == 0) {
        int run = 0;
        for (int b = 0; b < NB_SCAN; b++) { bpre[b] = run; run += g_bsum[b]; }
    }
    __syncthreads();
    int i = blockIdx.x * blockDim.x + t;
    if (i < NN) {
        int incl = g_incl[i] + bpre[i >> 10];
        g_off[i + 1] = incl;
        g_cur[i]     = incl - g_deg[i];
    }
    if (i == 0) g_off[0] = 0;
}

__global__ void k_scatter(const void* __restrict__ ei) {
    int e = blockIdx.x * blockDim.x + threadIdx.x;
    if (e < EE) {
        int is64 = g_is64;
        int d = load_idx(ei, (size_t)EE + e, is64);
        int s = load_idx(ei, (size_t)e, is64);
        if ((unsigned)d < NN && (unsigned)s < NN) {
            int pos = atomicAdd(&g_cur[d], 1);
            if ((unsigned)pos < EE) {
                g_perm[pos] = e;
                g_srcs[pos] = s;
            }
        }
    }
}

// ---------------- fp32 SGEMM 128x128x16, 8x8 register blocking --------------
// which: 0->g_q 1->g_k 2->g_v 3->dout
__global__ __launch_bounds__(256, 2)
void k_sgemm(const float* __restrict__ A, const float* __restrict__ B,
             const float* __restrict__ bias, float* __restrict__ dout,
             int which, int M) {
    float* Cout;
    switch (which) {
        case 0: Cout = g_q; break;
        case 1: Cout = g_k; break;
        case 2: Cout = g_v; break;
        default: Cout = dout; break;
    }

    __shared__ float As[16][128];
    __shared__ float Bs[16][128];

    int t  = threadIdx.x;
    int bm = blockIdx.x * 128;
    int bn = blockIdx.y * 128;
    int tx = t & 15, ty = t >> 4;

    float acc[8][8];
    #pragma unroll
    for (int i = 0; i < 8; i++)
        #pragma unroll
        for (int j = 0; j < 8; j++) acc[i][j] = 0.f;

    int ar = t >> 2,  ac = (t & 3) * 4;
    int bk = t >> 5,  bc = (t & 31) * 4;

    for (int k0 = 0; k0 < 256; k0 += 16) {
        #pragma unroll
        for (int i = 0; i < 2; i++) {
            int row = bm + ar + i * 64;
            int rr  = (row < M) ? row : (M - 1);
            float4 a = *(const float4*)(A + (size_t)rr * 256 + k0 + ac);
            As[ac + 0][ar + i * 64] = a.x;
            As[ac + 1][ar + i * 64] = a.y;
            As[ac + 2][ar + i * 64] = a.z;
            As[ac + 3][ar + i * 64] = a.w;
        }
        #pragma unroll
        for (int i = 0; i < 2; i++) {
            float4 b = *(const float4*)(B + (size_t)(k0 + bk + i * 8) * 256 + bn + bc);
            *(float4*)&Bs[bk + i * 8][bc] = b;
        }
        __syncthreads();
        #pragma unroll
        for (int kk = 0; kk < 16; kk++) {
            float ra[8], rb[8];
            *(float4*)(ra)     = *(float4*)&As[kk][ty * 8];
            *(float4*)(ra + 4) = *(float4*)&As[kk][ty * 8 + 4];
            *(float4*)(rb)     = *(float4*)&Bs[kk][tx * 8];
            *(float4*)(rb + 4) = *(float4*)&Bs[kk][tx * 8 + 4];
            #pragma unroll
            for (int i = 0; i < 8; i++)
                #pragma unroll
                for (int j = 0; j < 8; j++)
                    acc[i][j] = fmaf(ra[i], rb[j], acc[i][j]);
        }
        __syncthreads();
    }

    float bb[8];
    #pragma unroll
    for (int j = 0; j < 8; j++) bb[j] = bias[bn + tx * 8 + j];

    #pragma unroll
    for (int i = 0; i < 8; i++) {
        int row = bm + ty * 8 + i;
        if (row < M) {
            float* cptr = Cout + (size_t)row * 256 + bn + tx * 8;
            float4 o0, o1;
            o0.x = acc[i][0] + bb[0]; o0.y = acc[i][1] + bb[1];
            o0.z = acc[i][2] + bb[2]; o0.w = acc[i][3] + bb[3];
            o1.x = acc[i][4] + bb[4]; o1.y = acc[i][5] + bb[5];
            o1.z = acc[i][6] + bb[6]; o1.w = acc[i][7] + bb[7];
            *(float4*)(cptr)     = o0;
            *(float4*)(cptr + 4) = o1;
        }
    }
}

// ---------------- P GEMM: P[n,h,i] = sum_c q[n,h*32+c] * We[i,h*32+c] -------
__global__ __launch_bounds__(256)
void k_pgemm(const float* __restrict__ We) {
    __shared__ float qs[64][33];
    __shared__ float Wt[32][257];
    int h  = blockIdx.y;
    int n0 = blockIdx.x * 64;
    int t  = threadIdx.x;

    for (int idx = t; idx < 64 * 32; idx += 256) {
        int node = idx >> 5, c = idx & 31;
        int n = n0 + node;
        qs[node][c] = (n < NN) ? g_q[(size_t)n * 256 + h * 32 + c] : 0.f;
    }
    for (int idx = t; idx < 256 * 32; idx += 256) {
        int i = idx >> 5, c = idx & 31;
        Wt[c][i] = We[(size_t)i * 256 + h * 32 + c];
    }
    __syncthreads();

    int tx = t & 31;
    int ty = t >> 5;
    float acc[8][8];
    #pragma unroll
    for (int r = 0; r < 8; r++)
        #pragma unroll
        for (int ii = 0; ii < 8; ii++) acc[r][ii] = 0.f;

    #pragma unroll 4
    for (int c = 0; c < 32; c++) {
        float a[8], b[8];
        #pragma unroll
        for (int r = 0; r < 8; r++) a[r] = qs[ty * 8 + r][c];
        #pragma unroll
        for (int ii = 0; ii < 8; ii++) b[ii] = Wt[c][tx + ii * 32];
        #pragma unroll
        for (int r = 0; r < 8; r++)
            #pragma unroll
            for (int ii = 0; ii < 8; ii++)
                acc[r][ii] = fmaf(a[r], b[ii], acc[r][ii]);
    }

    #pragma unroll
    for (int r = 0; r < 8; r++) {
        int n = n0 + ty * 8 + r;
        if (n < NN) {
            float* Pr = g_P + ((size_t)n * 8 + h) * 256;
            #pragma unroll
            for (int ii = 0; ii < 8; ii++)
                Pr[tx + ii * 32] = acc[r][ii];
        }
    }
}

// ---------------- edge pass: cp.async 4-stage pipeline, online softmax ------
__device__ __forceinline__ void cp_async16(unsigned smem, const void* g) {
    asm volatile("cp.async.cg.shared.global [%0], [%1], 16;\n"
                 :: "r"(smem), "l"(g) : "memory");
}
__device__ __forceinline__ void cp_commit() {
    asm volatile("cp.async.commit_group;\n" ::: "memory");
}
template <int N>
__device__ __forceinline__ void cp_wait() {
    asm volatile("cp.async.wait_group %0;\n" :: "n"(N) : "memory");
}

__global__ __launch_bounds__(256)
void k_edge(const float* __restrict__ ea, float* __restrict__ out) {
    __shared__ float eas[EST][256];
    int n    = blockIdx.x;
    int t    = threadIdx.x;
    int h    = t >> 5;
    int lane = t & 31;

    int begin = g_off[n], end = g_off[n + 1];
    size_t nb = (size_t)n * 256 + h * 32 + lane;
    const float scale = 0.17677669529663687f;     // 1/sqrt(32)
    float qv = g_q[nb] * scale;

    const float* Pr = g_P + ((size_t)n * 8 + h) * 256;
    float preg[8];
    #pragma unroll
    for (int j = 0; j < 8; j++) preg[j] = __ldcs(Pr + j * 32 + lane) * scale;

    float m = -INFINITY, l = 0.f, vacc = 0.f;
    float A[8];
    #pragma unroll
    for (int j = 0; j < 8; j++) A[j] = 0.f;

    unsigned smem_row = (unsigned)__cvta_generic_to_shared(&eas[0][0]);
    int cth = t & 63;  // 64 copy threads x 16B cover a 1KB row

    // prefetch(ip): issue row copy for edge ip into stage ip%EST; always commit
    auto prefetch = [&](int ip) {
        if (ip < end && t < 64) {
            int eo = g_perm[ip];
            cp_async16(smem_row + (ip & (EST - 1)) * 1024 + cth * 16,
                       ea + (size_t)eo * 256 + cth * 4);
        }
        cp_commit();
    };

    #pragma unroll
    for (int j = 0; j < EST - 1; j++) prefetch(begin + j);

    for (int i = begin; i < end; i++) {
        cp_wait<EST - 2>();      // edge i's stage has landed
        __syncthreads();         // publish; also retires readers of stage (i-1)%EST
        prefetch(i + EST - 1);   // refill stage (i-1)%EST for edge i+EST-1

        int src = g_srcs[i];
        size_t sb = (size_t)src * 256 + h * 32 + lane;
        float kv = g_k[sb];
        float vv = g_v[sb];

        const float* eb = eas[i & (EST - 1)];
        float er[8];
        #pragma unroll
        for (int j = 0; j < 8; j++) er[j] = eb[j * 32 + lane];

        float s = qv * kv;
        #pragma unroll
        for (int j = 0; j < 8; j++) s = fmaf(preg[j], er[j], s);
        #pragma unroll
        for (int o = 16; o; o >>= 1) s += __shfl_xor_sync(0xffffffffu, s, o);

        float nm = fmaxf(m, s);
        float cf = __expf(m - nm);
        float p  = __expf(s - nm);
        l    = l * cf + p;
        vacc = vacc * cf + p * vv;
        #pragma unroll
        for (int j = 0; j < 8; j++) A[j] = fmaf(A[j], cf, p * er[j]);
        m = nm;
    }
    cp_wait<0>();

    float inv = (l > 0.f) ? (1.f / l) : 0.f;
    out[nb] += vacc * inv;
    float* Ar = g_A + ((size_t)n * 8 + h) * 256;
    #pragma unroll
    for (int j = 0; j < 8; j++) Ar[j * 32 + lane] = A[j] * inv;
}

// ---------------- A GEMM: out[n,h*32+c] += sum_i A[n,h,i] * We[i,h*32+c] ----
__global__ __launch_bounds__(256)
void k_agemm(const float* __restrict__ We, float* __restrict__ out) {
    __shared__ float As[64][65];
    __shared__ float Ws[64][33];
    int h  = blockIdx.y;
    int n0 = blockIdx.x * 64;
    int t  = threadIdx.x;
    int tx = t & 31;
    int ty = t >> 5;

    float acc[8];
    #pragma unroll
    for (int r = 0; r < 8; r++) acc[r] = 0.f;

    for (int k0 = 0; k0 < 256; k0 += 64) {
        __syncthreads();
        for (int idx = t; idx < 64 * 64; idx += 256) {
            int node = idx >> 6, kk = idx & 63;
            int n = n0 + node;
            As[node][kk] = (n < NN)
                ? __ldcs(g_A + ((size_t)n * 8 + h) * 256 + k0 + kk) : 0.f;
        }
        for (int idx = t; idx < 64 * 32; idx += 256) {
            int kk = idx >> 5, c = idx & 31;
            Ws[kk][c] = We[(size_t)(k0 + kk) * 256 + h * 32 + c];
        }
        __syncthreads();
        #pragma unroll 8
        for (int kk = 0; kk < 64; kk++) {
            float b = Ws[kk][tx];
            #pragma unroll
            for (int r = 0; r < 8; r++)
                acc[r] = fmaf(As[ty * 8 + r][kk], b, acc[r]);
        }
    }

    #pragma unroll
    for (int r = 0; r < 8; r++) {
        int n = n0 + ty * 8 + r;
        if (n < NN)
            out[(size_t)n * 256 + h * 32 + tx] += acc[r];
    }
}

// ---------------- launch ----------------------------------------------------
extern "C" void kernel_launch(void* const* d_in, const int* in_sizes, int n_in,
                              void* d_out, int out_size) {
    const float* x  = (const float*)d_in[0];
    const void*  ei = d_in[1];
    const float* ea = (const float*)d_in[2];
    const float* Wq = (const float*)d_in[3];
    const float* bq = (const float*)d_in[4];
    const float* Wk = (const float*)d_in[5];
    const float* bk = (const float*)d_in[6];
    const float* Wv = (const float*)d_in[7];
    const float* bv = (const float*)d_in[8];
    const float* We = (const float*)d_in[9];
    const float* Ws = (const float*)d_in[10];
    const float* bs = (const float*)d_in[11];
    float* out = (float*)d_out;

    // 0-1) init (dtype sniff + zero degrees), histogram
    k_init<<<(NN + 255) / 256, 256>>>((const long long*)ei);
    k_hist<<<(EE + 255) / 256, 256>>>(ei);

    // 2-5) node GEMMs early (independent of sort; also lands in ncu window)
    dim3 gn((NN + 127) / 128, 2);
    k_sgemm<<<gn, 256>>>(x, Wq, bq, out, 0, NN);
    k_sgemm<<<gn, 256>>>(x, Wk, bk, out, 1, NN);
    k_sgemm<<<gn, 256>>>(x, Wv, bv, out, 2, NN);
    k_sgemm<<<gn, 256>>>(x, Ws, bs, out, 3, NN);

    // 6-8) finish CSR sort
    k_scan1<<<NB_SCAN, 1024>>>();
    k_scan23<<<(NN + 255) / 256, 256>>>();
    k_scatter<<<(EE + 255) / 256, 256>>>(ei);

    // 9) P[n,h,i] = We_h @ q_h
    dim3 gp((NN + 63) / 64, 8);
    k_pgemm<<<gp, 256>>>(We);

    // 10) pipelined edge pass
    k_edge<<<NN, 256>>>(ea, out);

    // 11) out += A @ We
    k_agemm<<<gp, 256>>>(We, out);
}